// round 11
// baseline (speedup 1.0000x reference)
#include <cuda_runtime.h>
#include <cuda_bf16.h>
#include <mma.h>
#include <math.h>

// GRU: B=128, T=512, I=256, H=512. out = final h [1,128,512] fp32.
// Persistent kernel, 128 CTAs (4 batch x 32 j). Pre-phase: x@W_ih^T for ALL t
// precomputed into g_xg (fp32, CTA-local layout), W_ih frags held in regs.
// Main loop: h-projection only (wmma bf16 hi/lo 3-product), 16 mma warps,
// per-batch-group (32-CTA) barriers, h_old carried in registers.

using namespace nvcuda;

#define BATCH 128
#define TT    512
#define II    256
#define HH    512
#define GB    4
#define GJ    32
#define BC    32
#define JC    16
#define NCTA  128
#define NSYNC 32          // CTAs per sync group (same gb)
#define NTHR  512

#define USTRIDE 264       // u16 per U row (256+8)
#define WHHS    520       // u16 per W_hh row (512+8)
#define WIHS    264       // u16 per W_ih row (256+8)

// SMEM byte offsets
#define SM_WHH_H 0                      // 48*520*2 = 49920
#define SM_WHH_L 49920                  // 49920
#define SM_UH1   99840                  // 32*264*2 = 16896  (h cols 0-255 hi)
#define SM_UL1   116736
#define SM_UH0   133632                 // h cols 256-511 hi (pre-phase: x hi)
#define SM_UL0   150528
#define SM_DRED  167424                 // 48 tiles * 1024 B = 49152
#define SM_BS    216576                 // 96 f32 + pad
#define SMEM_BYTES 217088
// pre-phase temporaries (dead before first use of their real owners)
#define SM_WIH_H SM_UH1                 // 48*264*2 = 25344 (spans UH1+part UL1)
#define SM_WIH_L SM_DRED                // 25344 <= 49152

__device__ float          g_xg[(size_t)GJ*BATCH*TT*48];   // [gj][b][t][48]
__device__ unsigned short g_hsh[2][BATCH*HH];
__device__ unsigned short g_hsl[2][BATCH*HH];
__device__ unsigned int   g_cnt[GB*32];                   // padded per-gb
__device__ unsigned int   g_ph [GB*32];

__device__ __forceinline__ float sigm(float x) {
    return 1.0f / (1.0f + __expf(-x));
}
__device__ __forceinline__ unsigned short bhi(float v) {
    return __bfloat16_as_ushort(__float2bfloat16(v));
}
__device__ __forceinline__ unsigned short blo(float v) {
    __nv_bfloat16 h = __float2bfloat16(v);
    return __bfloat16_as_ushort(__float2bfloat16(v - __bfloat162float(h)));
}

extern "C" __global__ void __launch_bounds__(NTHR, 1)
gru_persistent_kernel(const float* __restrict__ x,      // [B, T, I]
                      const float* __restrict__ W_ih,   // [3H, I]
                      const float* __restrict__ W_hh,   // [3H, H]
                      const float* __restrict__ b_ih,   // [3H]
                      const float* __restrict__ b_hh,   // [3H]
                      float* __restrict__ out)          // [1, B, H]
{
    extern __shared__ char smem[];
    unsigned short* WhhH = (unsigned short*)(smem + SM_WHH_H);
    unsigned short* WhhL = (unsigned short*)(smem + SM_WHH_L);
    unsigned short* Uh1  = (unsigned short*)(smem + SM_UH1);
    unsigned short* Ul1  = (unsigned short*)(smem + SM_UL1);
    unsigned short* Uh0  = (unsigned short*)(smem + SM_UH0);
    unsigned short* Ul0  = (unsigned short*)(smem + SM_UL0);
    unsigned short* WihH = (unsigned short*)(smem + SM_WIH_H);
    unsigned short* WihL = (unsigned short*)(smem + SM_WIH_L);
    float* Dred = (float*)(smem + SM_DRED);
    float* B_s  = (float*)(smem + SM_BS);

    const int tid = threadIdx.x;
    const int bx  = blockIdx.x;
    const int gb  = bx & (GB - 1);
    const int gj  = bx >> 2;
    const int b0  = gb * BC;
    const int j0  = gj * JC;

    // relative-phase base for this gb group (read before any arrive; pre-phase
    // length >> launch skew makes this safe)
    unsigned base = 0;
    if (tid == 0) base = *((volatile unsigned*)&g_ph[gb * 32]);

    // ---- one-time: W_hh hi/lo (permanent), W_ih hi/lo (temp), biases ----
    for (int idx = tid; idx < 48 * 512; idx += NTHR) {
        int row = idx >> 9, col = idx & 511;
        int G = (row < 16) ? j0 + row
              : (row < 32) ? 512 + j0 + (row - 16)
                           : 1024 + j0 + (row - 32);
        float v = W_hh[G * HH + col];
        WhhH[row * WHHS + col] = bhi(v);
        WhhL[row * WHHS + col] = blo(v);
    }
    for (int idx = tid; idx < 48 * 256; idx += NTHR) {
        int row = idx >> 8, col = idx & 255;
        int G = (row < 16) ? j0 + row
              : (row < 32) ? 512 + j0 + (row - 16)
                           : 1024 + j0 + (row - 32);
        float v = W_ih[G * II + col];
        WihH[row * WIHS + col] = bhi(v);
        WihL[row * WIHS + col] = blo(v);
    }
    if (tid < 96) {
        int loc = tid % 48;
        int G = (loc < 16) ? j0 + loc
              : (loc < 32) ? 512 + j0 + (loc - 16)
                           : 1024 + j0 + (loc - 32);
        B_s[tid] = (tid < 48) ? b_hh[G] : b_ih[G];
    }
    __syncthreads();

    // ---- pre-phase warp roles: 12 mma warps = 2 btile x 3 gate x 2 kh ----
    const int w     = tid >> 5;
    const int kh    = w & 1;
    const int tau   = w >> 1;          // 0..5 for w<12
    const int btileP = tau / 3;
    const int ntileP = tau % 3;

    wmma::fragment<wmma::matrix_a, 16, 16, 16, __nv_bfloat16, wmma::row_major> fa_h, fa_l;
    wmma::fragment<wmma::matrix_b, 16, 16, 16, __nv_bfloat16, wmma::col_major> fb_h, fb_l;
    wmma::fragment<wmma::matrix_b, 16, 16, 16, __nv_bfloat16, wmma::col_major> fwh[8], fwl[8];
    wmma::fragment<wmma::accumulator, 16, 16, 16, float> facc, acc0, acc1, acc2;

    if (w < 12) {
        const __nv_bfloat16* Bh = (const __nv_bfloat16*)WihH + ntileP * 16 * WIHS;
        const __nv_bfloat16* Bl = (const __nv_bfloat16*)WihL + ntileP * 16 * WIHS;
        #pragma unroll
        for (int i = 0; i < 8; i++) {
            int ks = kh * 8 + i;
            wmma::load_matrix_sync(fwh[i], Bh + ks * 16, WIHS);
            wmma::load_matrix_sync(fwl[i], Bl + ks * 16, WIHS);
        }
    }
    __syncthreads();   // W_ih consumed into regs; Dred/UH1 regions now free

    // thread helper indices
    const int srow = tid >> 4;          // 0..31
    const int sk16 = (tid & 15) * 16;   // 16 u16 per plane
    const int sk32 = (tid & 15) * 32;
    const int jj   = tid & 15;
    const int bb   = tid >> 4;          // 0..31
    const int btl  = bb >> 4;
    const int loc  = (bb & 15) * 16 + jj;

    const size_t xg_cta = (((size_t)gj * BATCH + b0 + bb) * TT) * 48;

    // ---- pre-phase: g_xg[b][t][48] = x(t) @ W_ih^T + b_ih (no barriers) ----
    for (int t = 0; t < TT; t++) {
        // stage x(t) hi/lo into Uh0/Ul0
        {
            const float* xs = x + ((size_t)(b0 + srow) * TT + t) * II + sk16;
            float vv[16];
            *(float4*)(vv + 0)  = *(const float4*)(xs + 0);
            *(float4*)(vv + 4)  = *(const float4*)(xs + 4);
            *(float4*)(vv + 8)  = *(const float4*)(xs + 8);
            *(float4*)(vv + 12) = *(const float4*)(xs + 12);
            unsigned hp[8], lp[8];
            #pragma unroll
            for (int k2 = 0; k2 < 8; k2++) {
                unsigned h0 = bhi(vv[2*k2]), h1 = bhi(vv[2*k2+1]);
                unsigned l0 = blo(vv[2*k2]), l1 = blo(vv[2*k2+1]);
                hp[k2] = h0 | (h1 << 16);
                lp[k2] = l0 | (l1 << 16);
            }
            uint4* dh = (uint4*)(Uh0 + srow * USTRIDE + sk16);
            uint4* dl = (uint4*)(Ul0 + srow * USTRIDE + sk16);
            dh[0] = make_uint4(hp[0], hp[1], hp[2], hp[3]);
            dh[1] = make_uint4(hp[4], hp[5], hp[6], hp[7]);
            dl[0] = make_uint4(lp[0], lp[1], lp[2], lp[3]);
            dl[1] = make_uint4(lp[4], lp[5], lp[6], lp[7]);
        }
        __syncthreads();

        if (w < 12) {
            wmma::fill_fragment(facc, 0.0f);
            const __nv_bfloat16* Ah = (const __nv_bfloat16*)Uh0 + btileP * 16 * USTRIDE;
            const __nv_bfloat16* Al = (const __nv_bfloat16*)Ul0 + btileP * 16 * USTRIDE;
            #pragma unroll
            for (int i = 0; i < 8; i++) {
                int ks = kh * 8 + i;
                wmma::load_matrix_sync(fa_h, Ah + ks * 16, USTRIDE);
                wmma::load_matrix_sync(fa_l, Al + ks * 16, USTRIDE);
                wmma::mma_sync(facc, fa_h, fwh[i], facc);
                wmma::mma_sync(facc, fa_h, fwl[i], facc);
                wmma::mma_sync(facc, fa_l, fwh[i], facc);
            }
            wmma::store_matrix_sync(Dred + (tau * 2 + kh) * 256, facc, 16, wmma::mem_row_major);
        }
        __syncthreads();

        // write 3 gate values (fp32, b_ih folded)
        {
            const size_t xb = xg_cta + (size_t)t * 48;
            #pragma unroll
            for (int g = 0; g < 3; g++) {
                float v = Dred[((btl * 3 + g) * 2 + 0) * 256 + loc]
                        + Dred[((btl * 3 + g) * 2 + 1) * 256 + loc]
                        + B_s[48 + g * 16 + jj];
                g_xg[xb + g * 16 + jj] = v;
            }
        }
        __syncthreads();
    }

    // zero this CTA's block of the parity-0 h planes
    for (int i = tid; i < BC * JC; i += NTHR) {
        int b = i >> 4, j = i & 15;
        int gi = (b0 + b) * HH + j0 + j;
        g_hsh[0][gi] = 0;
        g_hsl[0][gi] = 0;
    }

    // ---- init arrive for this gb group (phase -> base+1) ----
    __syncthreads();
    if (tid == 0) {
        __threadfence();
        if (atomicAdd(&g_cnt[gb * 32], 1u) == NSYNC - 1u) {
            g_cnt[gb * 32] = 0;
            __threadfence();
            *((volatile unsigned*)&g_ph[gb * 32]) = base + 1u;
        }
    }

    // ---- main loop: h projection only ----
    const int btile = w >> 3;           // 16 mma warps: 2 btile x 8 kw
    const int kw    = w & 7;
    const float bhr = B_s[jj];
    const float bhz = B_s[16 + jj];
    const float bhn = B_s[32 + jj];
    float hold = 0.0f;

    for (int t = 0; t < TT; t++) {
        const int rp = t & 1;
        const int wp = rp ^ 1;

        // prefetch x_gates (independent of barrier)
        const size_t xb = xg_cta + (size_t)t * 48;
        float xr  = g_xg[xb + jj];
        float xz  = g_xg[xb + 16 + jj];
        float xnv = g_xg[xb + 32 + jj];

        // wait for peers' h(t-1)
        if (tid == 0) {
            while ((unsigned)(*((volatile unsigned*)&g_ph[gb * 32]) - base) < (unsigned)(t + 1)) {
                __nanosleep(32);
            }
            __threadfence();
        }
        __syncthreads();

        // stage h planes: cols 0-255 -> Uh1/Ul1, 256-511 -> Uh0/Ul0
        {
            const int goff = (b0 + srow) * HH + sk32;
            const uint4* sh = (const uint4*)(g_hsh[rp] + goff);
            const uint4* sl = (const uint4*)(g_hsl[rp] + goff);
            uint4 *dh, *dl;
            if (sk32 < 256) {
                dh = (uint4*)(Uh1 + srow * USTRIDE + sk32);
                dl = (uint4*)(Ul1 + srow * USTRIDE + sk32);
            } else {
                dh = (uint4*)(Uh0 + srow * USTRIDE + (sk32 - 256));
                dl = (uint4*)(Ul0 + srow * USTRIDE + (sk32 - 256));
            }
            dh[0] = sh[0]; dh[1] = sh[1]; dh[2] = sh[2]; dh[3] = sh[3];
            dl[0] = sl[0]; dl[1] = sl[1]; dl[2] = sl[2]; dl[3] = sl[3];
        }
        __syncthreads();

        // mma: all 16 warps; warp covers 3 gates x 4 ks (K-slice kw)
        {
            const __nv_bfloat16 *Ah, *Al;
            int ksl0;
            if (kw < 4) {
                Ah = (const __nv_bfloat16*)Uh1; Al = (const __nv_bfloat16*)Ul1;
                ksl0 = kw * 4;
            } else {
                Ah = (const __nv_bfloat16*)Uh0; Al = (const __nv_bfloat16*)Ul0;
                ksl0 = (kw - 4) * 4;
            }
            Ah += btile * 16 * USTRIDE;
            Al += btile * 16 * USTRIDE;
            const int ksg0 = kw * 4;
            const __nv_bfloat16* Wh0 = (const __nv_bfloat16*)WhhH;
            const __nv_bfloat16* Wl0 = (const __nv_bfloat16*)WhhL;

            wmma::fill_fragment(acc0, 0.0f);
            wmma::fill_fragment(acc1, 0.0f);
            wmma::fill_fragment(acc2, 0.0f);
            #pragma unroll
            for (int i = 0; i < 4; i++) {
                wmma::load_matrix_sync(fa_h, Ah + (ksl0 + i) * 16, USTRIDE);
                wmma::load_matrix_sync(fa_l, Al + (ksl0 + i) * 16, USTRIDE);
                const int kc = (ksg0 + i) * 16;
                wmma::load_matrix_sync(fb_h, Wh0 + 0 * 16 * WHHS + kc, WHHS);
                wmma::load_matrix_sync(fb_l, Wl0 + 0 * 16 * WHHS + kc, WHHS);
                wmma::mma_sync(acc0, fa_h, fb_h, acc0);
                wmma::mma_sync(acc0, fa_h, fb_l, acc0);
                wmma::mma_sync(acc0, fa_l, fb_h, acc0);
                wmma::load_matrix_sync(fb_h, Wh0 + 1 * 16 * WHHS + kc, WHHS);
                wmma::load_matrix_sync(fb_l, Wl0 + 1 * 16 * WHHS + kc, WHHS);
                wmma::mma_sync(acc1, fa_h, fb_h, acc1);
                wmma::mma_sync(acc1, fa_h, fb_l, acc1);
                wmma::mma_sync(acc1, fa_l, fb_h, acc1);
                wmma::load_matrix_sync(fb_h, Wh0 + 2 * 16 * WHHS + kc, WHHS);
                wmma::load_matrix_sync(fb_l, Wl0 + 2 * 16 * WHHS + kc, WHHS);
                wmma::mma_sync(acc2, fa_h, fb_h, acc2);
                wmma::mma_sync(acc2, fa_h, fb_l, acc2);
                wmma::mma_sync(acc2, fa_l, fb_h, acc2);
            }
            wmma::store_matrix_sync(Dred + (btile * 24 + 0 * 8 + kw) * 256, acc0, 16, wmma::mem_row_major);
            wmma::store_matrix_sync(Dred + (btile * 24 + 1 * 8 + kw) * 256, acc1, 16, wmma::mem_row_major);
            wmma::store_matrix_sync(Dred + (btile * 24 + 2 * 8 + kw) * 256, acc2, 16, wmma::mem_row_major);
        }
        __syncthreads();

        // gates + h update (h_old carried in register)
        {
            float dr = 0.0f, dz = 0.0f, dn = 0.0f;
            #pragma unroll
            for (int k2 = 0; k2 < 8; k2++) {
                dr += Dred[(btl * 24 + k2) * 256 + loc];
                dz += Dred[(btl * 24 + 8 + k2) * 256 + loc];
                dn += Dred[(btl * 24 + 16 + k2) * 256 + loc];
            }
            float r = sigm(xr + dr + bhr);
            float z = sigm(xz + dz + bhz);
            float n = tanhf(xnv + r * (dn + bhn));
            hold = n + z * (hold - n);
            const int gi = (b0 + bb) * HH + j0 + jj;
            g_hsh[wp][gi] = bhi(hold);
            g_hsl[wp][gi] = blo(hold);
            if (t == TT - 1) out[gi] = hold;
        }
        __syncthreads();

        // arrive
        if (tid == 0) {
            __threadfence();
            if (atomicAdd(&g_cnt[gb * 32], 1u) == NSYNC - 1u) {
                g_cnt[gb * 32] = 0;
                __threadfence();
                *((volatile unsigned*)&g_ph[gb * 32]) = base + (unsigned)(t + 2);
            }
        }
    }
}

extern "C" void kernel_launch(void* const* d_in, const int* in_sizes, int n_in,
                              void* d_out, int out_size) {
    (void)in_sizes; (void)n_in; (void)out_size;
    cudaFuncSetAttribute(gru_persistent_kernel,
                         cudaFuncAttributeMaxDynamicSharedMemorySize, SMEM_BYTES);
    gru_persistent_kernel<<<NCTA, NTHR, SMEM_BYTES>>>(
        (const float*)d_in[0],
        (const float*)d_in[1],
        (const float*)d_in[2],
        (const float*)d_in[3],
        (const float*)d_in[4],
        (float*)d_out);
}